// round 15
// baseline (speedup 1.0000x reference)
#include <cuda_runtime.h>
#include <cuda_bf16.h>
#include <cstdint>
#include <math.h>

using bf16 = __nv_bfloat16;
#define DINLINE __device__ __forceinline__

// ---------------- problem dims ----------------
#define D_IN 1024
#define HID  512
#define WAYS 64
#define S_N  1024
#define Q_N  4096
#define M_ALL (S_N + Q_N)

// int8 quantization scales
#define SA_I 256.0f              // relation A = relu(qp+pp)
#define SB_I 1024.0f             // R2 weights
#define INV_SASB (1.0f / (256.0f * 1024.0f))
#define SX_I 32.0f               // encoder inputs
#define SW1_I 1024.0f            // W1 weights
#define INV_XW1 (1.0f / (32.0f * 1024.0f))

// ---------------- scratch (device globals; no allocation allowed) ----------------
__device__ __align__(256) signed char g_sx8[S_N * D_IN];
__device__ __align__(256) signed char g_qx8[Q_N * D_IN];
__device__ __align__(256) signed char g_W1t8[HID * D_IN];     // s8 [n][k]
__device__ __align__(256) bf16  g_W2t[HID * HID];
__device__ __align__(256) bf16  g_R1tT[HID * HID];            // R1w[:512] transposed
__device__ __align__(256) bf16  g_R1bT[HID * HID];            // R1w[512:] transposed
__device__ __align__(256) bf16  g_f1[M_ALL * HID];            // encoder layer1 out (S||Q)
__device__ __align__(256) bf16  g_f [M_ALL * HID];            // encoder layer2 out (S||Q)
__device__ __align__(256) bf16  g_qpb[Q_N * HID];             // q-half of R1 output
__device__ __align__(256) bf16  g_ppb[WAYS * HID];            // proto-half of R1 + R1b
__device__ __align__(256) signed char g_R2i8[HID * HID];      // R2w^T int8 [n][k]

// ---------------- PTX helpers ----------------
DINLINE uint32_t smem_u32(const void* p) { return (uint32_t)__cvta_generic_to_shared(p); }

DINLINE void cp16(uint32_t saddr, const void* g) {
    asm volatile("cp.async.cg.shared.global [%0], [%1], 16;\n" :: "r"(saddr), "l"(g));
}
DINLINE void cp_commit() { asm volatile("cp.async.commit_group;\n"); }
DINLINE void cp_wait0()  { asm volatile("cp.async.wait_group 0;\n"); }
DINLINE void cp_wait1()  { asm volatile("cp.async.wait_group 1;\n"); }
DINLINE void cp_wait2()  { asm volatile("cp.async.wait_group 2;\n"); }

DINLINE void ldmx4(uint32_t& r0, uint32_t& r1, uint32_t& r2, uint32_t& r3, uint32_t a) {
    asm volatile("ldmatrix.sync.aligned.m8n8.x4.shared.b16 {%0,%1,%2,%3}, [%4];\n"
                 : "=r"(r0), "=r"(r1), "=r"(r2), "=r"(r3) : "r"(a));
}
DINLINE void mma16816(float* c, uint32_t a0, uint32_t a1, uint32_t a2, uint32_t a3,
                      uint32_t b0, uint32_t b1) {
    asm volatile("mma.sync.aligned.m16n8k16.row.col.f32.bf16.bf16.f32 "
                 "{%0,%1,%2,%3}, {%4,%5,%6,%7}, {%8,%9}, {%0,%1,%2,%3};\n"
                 : "+f"(c[0]), "+f"(c[1]), "+f"(c[2]), "+f"(c[3])
                 : "r"(a0), "r"(a1), "r"(a2), "r"(a3), "r"(b0), "r"(b1));
}
DINLINE void mma16832_s8(int* c, uint32_t a0, uint32_t a1, uint32_t a2, uint32_t a3,
                         uint32_t b0, uint32_t b1) {
    asm volatile("mma.sync.aligned.m16n8k32.row.col.s32.s8.s8.s32 "
                 "{%0,%1,%2,%3}, {%4,%5,%6,%7}, {%8,%9}, {%0,%1,%2,%3};\n"
                 : "+r"(c[0]), "+r"(c[1]), "+r"(c[2]), "+r"(c[3])
                 : "r"(a0), "r"(a1), "r"(a2), "r"(a3), "r"(b0), "r"(b1));
}

DINLINE uint32_t pack_s8x4(int i0, int i1, int i2, int i3) {
    uint32_t t, d;
    asm("cvt.pack.sat.s8.s32.b32 %0, %1, %2, 0;" : "=r"(t) : "r"(i3), "r"(i2));
    asm("cvt.pack.sat.s8.s32.b32 %0, %1, %2, %3;" : "=r"(d) : "r"(i1), "r"(i0), "r"(t));
    return d;
}

DINLINE void unpk8(uint4 u, float* f) {
    __nv_bfloat162 h; float2 t;
    *(uint32_t*)&h = u.x; t = __bfloat1622float2(h); f[0] = t.x; f[1] = t.y;
    *(uint32_t*)&h = u.y; t = __bfloat1622float2(h); f[2] = t.x; f[3] = t.y;
    *(uint32_t*)&h = u.z; t = __bfloat1622float2(h); f[4] = t.x; f[5] = t.y;
    *(uint32_t*)&h = u.w; t = __bfloat1622float2(h); f[6] = t.x; f[7] = t.y;
}

// ---------------- consolidated prestage kernels ----------------
// quantize support_x and query_x to int8 in one launch
__global__ void quant2_s8(const float* __restrict__ sx, const float* __restrict__ qx,
                          signed char* __restrict__ sx8, signed char* __restrict__ qx8) {
    int i = (blockIdx.x * blockDim.x + threadIdx.x) * 4;
    const float* in;
    signed char* out;
    if (i < S_N * D_IN) { in = sx + i; out = sx8 + i; }
    else {
        int j = i - S_N * D_IN;
        if (j >= Q_N * D_IN) return;
        in = qx + j; out = qx8 + j;
    }
    float4 v = *(const float4*)in;
    uint32_t p = pack_s8x4(__float2int_rn(v.x * SX_I), __float2int_rn(v.y * SX_I),
                           __float2int_rn(v.z * SX_I), __float2int_rn(v.w * SX_I));
    *(uint32_t*)out = p;
}

// all 5 weight transposes in one launch; blockIdx.z selects the job.
__global__ void prep_weights(const float* __restrict__ W1, const float* __restrict__ W2,
                             const float* __restrict__ R1w, const float* __restrict__ R2w,
                             signed char* __restrict__ W1t8, bf16* __restrict__ W2t,
                             bf16* __restrict__ R1tT, bf16* __restrict__ R1bT,
                             signed char* __restrict__ R2i8) {
    __shared__ float t[32][33];
    const int z = blockIdx.z;
    const float* src; void* dst; int K, koff, mode; float scale;
    switch (z) {
        case 0:  src = W1;  dst = W1t8; K = D_IN; koff = 0;   mode = 1; scale = SW1_I; break;
        case 1:  src = W2;  dst = W2t;  K = HID;  koff = 0;   mode = 0; scale = 0.f;   break;
        case 2:  src = R1w; dst = R1tT; K = HID;  koff = 0;   mode = 0; scale = 0.f;   break;
        case 3:  src = R1w; dst = R1bT; K = HID;  koff = HID; mode = 0; scale = 0.f;   break;
        default: src = R2w; dst = R2i8; K = HID;  koff = 0;   mode = 1; scale = SB_I;  break;
    }
    const int kb = blockIdx.x * 32;
    if (kb >= K) return;
    const int nb = blockIdx.y * 32;
    const int tx = threadIdx.x & 31, ty = threadIdx.x >> 5;   // 32 x 8
#pragma unroll
    for (int r = 0; r < 4; r++)
        t[ty + r * 8][tx] = src[(size_t)(koff + kb + ty + r * 8) * HID + nb + tx];
    __syncthreads();
#pragma unroll
    for (int r = 0; r < 4; r++) {
        float v = t[tx][ty + r * 8];
        size_t o = (size_t)(nb + ty + r * 8) * K + kb + tx;
        if (mode == 0) ((bf16*)dst)[o] = __float2bfloat16(v);
        else {
            int i = __float2int_rn(v * scale);
            i = max(-127, min(127, i));
            ((signed char*)dst)[o] = (signed char)i;
        }
    }
}

// prototypes + pp fused: one block per class, 512 threads.
// Phase 1: proto[h] = mean of support features for class w (fp32, into smem).
// Phase 2: pp[w][n] = sum_k proto[k] * R1bT[n][k] + R1b[n]  (fp32 FMA dot).
__global__ void protos_pp_k(const bf16* __restrict__ sf, const int* __restrict__ y,
                            const bf16* __restrict__ R1bT, const float* __restrict__ R1b,
                            bf16* __restrict__ ppb) {
    __shared__ int ys[S_N];
    __shared__ float spro[HID];
    const int w = blockIdx.x;
    const int tid = threadIdx.x;
    for (int i = tid; i < S_N; i += 512) ys[i] = y[i];
    __syncthreads();
    {
        float acc = 0.f;
        int cnt = 0;
        for (int s = 0; s < S_N; s++) {
            if (ys[s] == w) { acc += __bfloat162float(sf[(size_t)s * HID + tid]); cnt++; }
        }
        spro[tid] = acc / (float)(cnt > 0 ? cnt : 1);
    }
    __syncthreads();
    {
        const bf16* row = R1bT + (size_t)tid * HID;
        float a = 0.f;
        for (int k = 0; k < HID; k += 8) {
            float f[8];
            unpk8(*(const uint4*)(row + k), f);
#pragma unroll
            for (int j = 0; j < 8; j++) a += spro[k + j] * f[j];
        }
        ppb[(size_t)w * HID + tid] = __float2bfloat16(a + R1b[tid]);
    }
}

// ---------------- generic bf16 TN GEMM (HMMA; pre-stages) ----------------
// BM=128, BN=64, 3-stage cp.async pipeline (R13 ncu: with 2 stages the per-tile
// load latency was exposed — occ 21.5%, issue 18.9%, tensor only 18.3%).
// SMEM = 3*(128+64)*72*2 = 82944 B -> 2 CTAs/SM (regs ~104).
template <bool BIAS, bool RELU>
__global__ void __launch_bounds__(256, 2) gemm_k(
    const bf16* __restrict__ A, const bf16* __restrict__ Bt,
    const float* __restrict__ bias, bf16* __restrict__ outB,
    int M, int K)
{
    extern __shared__ bf16 sm[];
    bf16* As = sm;                 // [3][128][72]
    bf16* Bs = sm + 3 * 9216;      // [3][64][72]
    const int tid = threadIdx.x;
    const int m0 = blockIdx.y * 128, n0 = blockIdx.x * 64;
    const int wid = tid >> 5, lane = tid & 31;
    const int wm = wid >> 1, wn = wid & 1;      // 4 M-warps x 2 N-warps
    const int grp = lane >> 2, tig = lane & 3;
    const uint32_t as_b = smem_u32(As), bs_b = smem_u32(Bs);

    auto load_tile = [&](int st, int kt) {
#pragma unroll
        for (int i = tid; i < 1536; i += 256) {
            if (i < 1024) {
                int r  = i >> 3;
                int ks = (i & 7) << 3;
                int ar = m0 + r; if (ar >= M) ar = M - 1;
                cp16(as_b + (uint32_t)(st * 9216 + r * 72 + ks) * 2,
                     A + (size_t)ar * K + kt * 64 + ks);
            } else {
                int j  = i - 1024;
                int r  = j >> 3;
                int ks = (j & 7) << 3;
                cp16(bs_b + (uint32_t)(st * 4608 + r * 72 + ks) * 2,
                     Bt + (size_t)(n0 + r) * K + kt * 64 + ks);
            }
        }
        cp_commit();
    };

    float c[2][4][4];
#pragma unroll
    for (int a = 0; a < 2; a++)
#pragma unroll
        for (int b = 0; b < 4; b++)
#pragma unroll
            for (int e = 0; e < 4; e++) c[a][b][e] = 0.f;

    const int KT = K >> 6;
    load_tile(0, 0);
    if (KT > 1) load_tile(1, 1);
    for (int kt = 0; kt < KT; kt++) {
        if (kt + 2 < KT) { load_tile((kt + 2) % 3, kt + 2); cp_wait2(); }
        else if (kt + 1 < KT) { cp_wait1(); }
        else { cp_wait0(); }
        __syncthreads();
        int st = kt % 3;
#pragma unroll
        for (int k16 = 0; k16 < 4; k16++) {
            uint32_t afr[2][4];
            uint32_t abase = as_b + (uint32_t)((st * 9216 + (wm * 32 + (lane & 15)) * 72
                                    + k16 * 16 + ((lane >> 4) << 3)) * 2);
#pragma unroll
            for (int ms = 0; ms < 2; ms++)
                ldmx4(afr[ms][0], afr[ms][1], afr[ms][2], afr[ms][3],
                      abase + (uint32_t)(ms * 16 * 72 * 2));
            uint32_t bfr[4][2];
#pragma unroll
            for (int ns = 0; ns < 4; ns++) {
                const bf16* p = Bs + st * 4608 + (wn * 32 + ns * 8 + grp) * 72
                                + k16 * 16 + 2 * tig;
                bfr[ns][0] = *(const uint32_t*)p;
                bfr[ns][1] = *(const uint32_t*)(p + 8);
            }
#pragma unroll
            for (int ms = 0; ms < 2; ms++)
#pragma unroll
                for (int ns = 0; ns < 4; ns++)
                    mma16816(c[ms][ns], afr[ms][0], afr[ms][1], afr[ms][2], afr[ms][3],
                             bfr[ns][0], bfr[ns][1]);
        }
        __syncthreads();
    }

#pragma unroll
    for (int ms = 0; ms < 2; ms++) {
#pragma unroll
        for (int i = 0; i < 4; i++) {
            int row = m0 + wm * 32 + ms * 16 + grp + ((i >> 1) << 3);
            if (row < M) {
#pragma unroll
                for (int ns = 0; ns < 4; ns++) {
                    int col = n0 + wn * 32 + ns * 8 + tig * 2 + (i & 1);
                    float v = c[ms][ns][i];
                    if (BIAS) v += bias[col];
                    if (RELU) v = fmaxf(v, 0.f);
                    outB[(size_t)row * HID + col] = __float2bfloat16(v);
                }
            }
        }
    }
}

// ---------------- int8 GEMM: merged encoder layer 1 (support || query) ----------------
// BM=128, BN=64, 3-stage pipeline. M = 5120, grid 8x40=320.
#define G1A_STG 16384
#define G1B_OFF (3 * G1A_STG)
#define G1B_STRD 144
#define G1B_STG 9216
#define G1_TOTAL (G1B_OFF + 3 * G1B_STG)

__global__ void __launch_bounds__(256, 2) gemm1_i8(
    const signed char* __restrict__ Asup, const signed char* __restrict__ Aqry,
    const signed char* __restrict__ B8,
    const float* __restrict__ bias, bf16* __restrict__ outB)
{
    extern __shared__ __align__(128) char sm8[];
    char* As = sm8;
    char* Bs = sm8 + G1B_OFF;
    const int tid = threadIdx.x;
    const int wid = tid >> 5, lane = tid & 31;
    const int wm = wid >> 1, wn = wid & 1;      // 4 M-warps x 2 N-warps
    const int grp = lane >> 2, tig = lane & 3;
    const int m0 = blockIdx.y * 128, n0 = blockIdx.x * 64;
    const signed char* A8 = (m0 < S_N) ? (Asup + (size_t)m0 * D_IN)
                                       : (Aqry + (size_t)(m0 - S_N) * D_IN);
    const uint32_t as_b = smem_u32(As), bs_b = smem_u32(Bs);

    auto load_tile = [&](int st, int kt) {
#pragma unroll
        for (int j = 0; j < 4; j++) {
            int idx = j * 256 + tid;
            int r = idx >> 3, c = idx & 7;
            cp16(as_b + (uint32_t)(st * G1A_STG + r * 128 + (((c ^ r) & 7) << 4)),
                 A8 + (size_t)r * D_IN + kt * 128 + c * 16);
        }
#pragma unroll
        for (int j = 0; j < 2; j++) {
            int idx = j * 256 + tid;
            int r = idx >> 3, c = idx & 7;
            cp16(bs_b + (uint32_t)(st * G1B_STG + r * G1B_STRD + c * 16),
                 B8 + (size_t)(n0 + r) * D_IN + kt * 128 + c * 16);
        }
        cp_commit();
    };

    int ci[2][4][4];
#pragma unroll
    for (int a = 0; a < 2; a++)
#pragma unroll
        for (int b = 0; b < 4; b++)
#pragma unroll
            for (int e = 0; e < 4; e++) ci[a][b][e] = 0;

    load_tile(0, 0);
    load_tile(1, 1);
    for (int kt = 0; kt < 8; kt++) {
        if (kt + 2 < 8) { load_tile((kt + 2) % 3, kt + 2); cp_wait2(); }
        else if (kt + 1 < 8) { cp_wait1(); }
        else { cp_wait0(); }
        __syncthreads();
        const int st = kt % 3;
#pragma unroll
        for (int k32 = 0; k32 < 4; k32++) {
            uint32_t afr[2][4];
            {
                const int arow0 = wm * 32 + (lane & 15);
                const int achk  = k32 * 2 + (lane >> 4);
#pragma unroll
                for (int ms = 0; ms < 2; ms++) {
                    const int arow = arow0 + ms * 16;
                    uint32_t aaddr = as_b + (uint32_t)(st * G1A_STG + arow * 128
                                   + (((achk ^ arow) & 7) << 4));
                    ldmx4(afr[ms][0], afr[ms][1], afr[ms][2], afr[ms][3], aaddr);
                }
            }
            uint32_t bfr[4][2];
#pragma unroll
            for (int ns = 0; ns < 4; ns++) {
                const char* p = Bs + st * G1B_STG
                              + (wn * 32 + ns * 8 + grp) * G1B_STRD
                              + k32 * 32 + tig * 4;
                bfr[ns][0] = *(const uint32_t*)p;
                bfr[ns][1] = *(const uint32_t*)(p + 16);
            }
#pragma unroll
            for (int ms = 0; ms < 2; ms++)
#pragma unroll
                for (int ns = 0; ns < 4; ns++)
                    mma16832_s8(ci[ms][ns], afr[ms][0], afr[ms][1], afr[ms][2], afr[ms][3],
                                bfr[ns][0], bfr[ns][1]);
        }
        __syncthreads();
    }

#pragma unroll
    for (int ms = 0; ms < 2; ms++) {
#pragma unroll
        for (int i = 0; i < 4; i++) {
            int row = m0 + wm * 32 + ms * 16 + grp + ((i >> 1) << 3);
#pragma unroll
            for (int ns = 0; ns < 4; ns++) {
                int col = n0 + wn * 32 + ns * 8 + tig * 2 + (i & 1);
                float v = (float)ci[ms][ns][i] * INV_XW1 + bias[col];
                v = fmaxf(v, 0.f);
                outB[(size_t)row * HID + col] = __float2bfloat16(v);
            }
        }
    }
}

// ---------------- int8 fused relation kernel (unchanged — R7 win) ----------------
#define RELA_OFF   0
#define RELB_OFF   65536
#define RELB_STG   18432
#define RELB_STRD  144
#define RELR2B_OFF 102400
#define RELR3W_OFF 104448
#define RELRED_OFF 106496
#define REL_TOTAL  108544

__global__ void __launch_bounds__(256, 2) relation_i8(
    const bf16* __restrict__ qpb, const bf16* __restrict__ ppb,
    const signed char* __restrict__ Bi8,
    const float* __restrict__ R2b, const float* __restrict__ R3w,
    const float* __restrict__ R3b, float* __restrict__ out)
{
    extern __shared__ __align__(128) char sm8[];
    char*  As8  = sm8 + RELA_OFF;
    char*  Bs8  = sm8 + RELB_OFF;
    float* sR2b = (float*)(sm8 + RELR2B_OFF);
    float* sR3w = (float*)(sm8 + RELR3W_OFF);
    float* red  = (float*)(sm8 + RELRED_OFF);
    const uint32_t as_b = smem_u32(As8);
    const uint32_t bs_b = smem_u32(Bs8);
    const int tid = threadIdx.x;
    const int wid = tid >> 5, lane = tid & 31;
    const int wm = wid >> 2, wn = wid & 3;
    const int grp = lane >> 2, tig = lane & 3;
    const int q0 = blockIdx.x * 2;

    auto loadB = [&](int flat) {
        int st = flat & 1, p = flat >> 2, kt = flat & 3;
#pragma unroll
        for (int j = 0; j < 4; j++) {
            int idx = j * 256 + tid;
            int r = idx >> 3, cc = idx & 7;
            cp16(bs_b + (uint32_t)(st * RELB_STG + r * RELB_STRD + cc * 16),
                 Bi8 + (size_t)(p * 128 + r) * HID + kt * 128 + cc * 16);
        }
        cp_commit();
    };

    loadB(0);

    for (int i = tid; i < HID; i += 256) { sR2b[i] = R2b[i]; sR3w[i] = R3w[i]; }

    // ---- build A: As[row][k] = sat_s8(relu(qp[q][k]+pp[w][k]) * SA_I), swizzled ----
    {
        const int c = tid & 31;
        const int wg = tid >> 5;
        float qv[2][16];
#pragma unroll
        for (int qi = 0; qi < 2; qi++) {
            const bf16* p = qpb + (size_t)(q0 + qi) * HID + c * 16;
            unpk8(*(const uint4*)p, qv[qi]);
            unpk8(*(const uint4*)(p + 8), qv[qi] + 8);
        }
        for (int w = wg * 8; w < wg * 8 + 8; w++) {
            float pv[16];
            const bf16* p = ppb + (size_t)w * HID + c * 16;
            unpk8(*(const uint4*)p, pv);
            unpk8(*(const uint4*)(p + 8), pv + 8);
#pragma unroll
            for (int qi = 0; qi < 2; qi++) {
                int row = qi * 64 + w;
                uint32_t pk[4];
#pragma unroll
                for (int g = 0; g < 4; g++) {
                    int ii[4];
#pragma unroll
                    for (int e = 0; e < 4; e++) {
                        float f = fmaxf(qv[qi][g * 4 + e] + pv[g * 4 + e], 0.f) * SA_I;
                        ii[e] = __float2int_rn(f);
                    }
                    pk[g] = pack_s8x4(ii[0], ii[1], ii[2], ii[3]);
                }
                uint32_t off = (uint32_t)(row * 512 + ((c >> 3) << 7) + (((c ^ row) & 7) << 4));
                *(uint4*)(As8 + off) = make_uint4(pk[0], pk[1], pk[2], pk[3]);
            }
        }
    }

    float rp[8];
#pragma unroll
    for (int j = 0; j < 8; j++) rp[j] = 0.f;

    for (int pass = 0; pass < 4; pass++) {
        const int n0 = pass * 128;
        int ci[4][4][4];
#pragma unroll
        for (int a = 0; a < 4; a++)
#pragma unroll
            for (int b = 0; b < 4; b++)
#pragma unroll
                for (int e = 0; e < 4; e++) ci[a][b][e] = 0;

        for (int kt = 0; kt < 4; kt++) {
            const int flat = pass * 4 + kt;
            if (flat + 1 < 16) { loadB(flat + 1); cp_wait1(); }
            else               { cp_wait0(); }
            __syncthreads();
            const int st = flat & 1;
#pragma unroll
            for (int k32 = 0; k32 < 4; k32++) {
                const int cbase = kt * 8 + k32 * 2;
                uint32_t afr[4][4];
                {
                    const int arow0 = wm * 64 + (lane & 15);
                    const int achk  = cbase + (lane >> 4);
#pragma unroll
                    for (int ms = 0; ms < 4; ms++) {
                        const int arow = arow0 + ms * 16;
                        uint32_t aaddr = as_b + (uint32_t)(arow * 512 + ((achk >> 3) << 7)
                                       + (((achk ^ arow) & 7) << 4));
                        ldmx4(afr[ms][0], afr[ms][1], afr[ms][2], afr[ms][3], aaddr);
                    }
                }
                uint32_t bfr[4][2];
#pragma unroll
                for (int ns = 0; ns < 4; ns++) {
                    const char* p = Bs8 + st * RELB_STG
                                  + (wn * 32 + ns * 8 + grp) * RELB_STRD
                                  + k32 * 32 + tig * 4;
                    bfr[ns][0] = *(const uint32_t*)p;
                    bfr[ns][1] = *(const uint32_t*)(p + 16);
                }
#pragma unroll
                for (int ms = 0; ms < 4; ms++)
#pragma unroll
                    for (int ns = 0; ns < 4; ns++)
                        mma16832_s8(ci[ms][ns], afr[ms][0], afr[ms][1], afr[ms][2], afr[ms][3],
                                    bfr[ns][0], bfr[ns][1]);
            }
            __syncthreads();
        }

#pragma unroll
        for (int ns = 0; ns < 4; ns++) {
            int colbase = n0 + wn * 32 + ns * 8 + tig * 2;
            float bb0 = sR2b[colbase], bb1 = sR2b[colbase + 1];
            float w0 = sR3w[colbase],  w1 = sR3w[colbase + 1];
#pragma unroll
            for (int ms = 0; ms < 4; ms++) {
                rp[ms * 2 + 0] += fmaxf((float)ci[ms][ns][0] * INV_SASB + bb0, 0.f) * w0
                                + fmaxf((float)ci[ms][ns][1] * INV_SASB + bb1, 0.f) * w1;
                rp[ms * 2 + 1] += fmaxf((float)ci[ms][ns][2] * INV_SASB + bb0, 0.f) * w0
                                + fmaxf((float)ci[ms][ns][3] * INV_SASB + bb1, 0.f) * w1;
            }
        }
    }

#pragma unroll
    for (int j = 0; j < 8; j++) {
        rp[j] += __shfl_xor_sync(0xffffffffu, rp[j], 1);
        rp[j] += __shfl_xor_sync(0xffffffffu, rp[j], 2);
    }
    if (tig == 0) {
#pragma unroll
        for (int j = 0; j < 8; j++) {
            int row = wm * 64 + (j >> 1) * 16 + grp + (j & 1) * 8;
            red[row * 4 + wn] = rp[j];
        }
    }
    __syncthreads();
    if (tid < 128) {
        float s = red[tid * 4 + 0] + red[tid * 4 + 1] + red[tid * 4 + 2] + red[tid * 4 + 3]
                + R3b[0];
        out[(size_t)blockIdx.x * 128 + tid] = 1.f / (1.f + expf(-s));
    }
}

// ---------------- host launcher ----------------
extern "C" void kernel_launch(void* const* d_in, const int* in_sizes, int n_in,
                              void* d_out, int out_size)
{
    (void)in_sizes; (void)n_in; (void)out_size;
    const float* support_x = (const float*)d_in[0];
    const int*   support_y = (const int*)d_in[1];
    const float* query_x   = (const float*)d_in[2];
    const float* W1  = (const float*)d_in[3];
    const float* b1  = (const float*)d_in[4];
    const float* W2  = (const float*)d_in[5];
    const float* b2  = (const float*)d_in[6];
    const float* R1w = (const float*)d_in[7];
    const float* R1b = (const float*)d_in[8];
    const float* R2w = (const float*)d_in[9];
    const float* R2b = (const float*)d_in[10];
    const float* R3w = (const float*)d_in[11];
    const float* R3b = (const float*)d_in[12];
    float* out = (float*)d_out;

    bf16 *W2t, *R1tT, *R1bT, *f1, *f, *qpb, *ppb;
    signed char *R2i8, *sx8, *qx8, *W1t8;
    cudaGetSymbolAddress((void**)&sx8, g_sx8);
    cudaGetSymbolAddress((void**)&qx8, g_qx8);
    cudaGetSymbolAddress((void**)&W1t8, g_W1t8);
    cudaGetSymbolAddress((void**)&W2t, g_W2t);
    cudaGetSymbolAddress((void**)&R1tT, g_R1tT);
    cudaGetSymbolAddress((void**)&R1bT, g_R1bT);
    cudaGetSymbolAddress((void**)&f1, g_f1);
    cudaGetSymbolAddress((void**)&f,  g_f);
    cudaGetSymbolAddress((void**)&qpb, g_qpb);
    cudaGetSymbolAddress((void**)&ppb, g_ppb);
    cudaGetSymbolAddress((void**)&R2i8, g_R2i8);

    const int GEMM_SMEM = 3 * (9216 + 4608) * 2;  // 82944 B
    cudaFuncSetAttribute(gemm_k<true,  true >, cudaFuncAttributeMaxDynamicSharedMemorySize, GEMM_SMEM);
    cudaFuncSetAttribute(gemm_k<false, false>, cudaFuncAttributeMaxDynamicSharedMemorySize, GEMM_SMEM);
    cudaFuncSetAttribute(gemm1_i8, cudaFuncAttributeMaxDynamicSharedMemorySize, G1_TOTAL);
    cudaFuncSetAttribute(relation_i8, cudaFuncAttributeMaxDynamicSharedMemorySize, REL_TOTAL);

    // 1) quantize both inputs (one launch)
    quant2_s8<<<(M_ALL * D_IN / 4 + 255) / 256, 256>>>(support_x, query_x, sx8, qx8);

    // 2) all weight transposes (one launch)
    prep_weights<<<dim3(32, 16, 5), 256>>>(W1, W2, R1w, R2w, W1t8, W2t, R1tT, R1bT, R2i8);

    // 3) merged encoder layer 1 (int8, S || Q)
    gemm1_i8<<<dim3(8, M_ALL / 128), 256, G1_TOTAL>>>(sx8, qx8, W1t8, b1, f1);

    // 4) merged encoder layer 2 (bf16, S || Q)
    gemm_k<true, true><<<dim3(8, M_ALL / 128), 256, GEMM_SMEM>>>(f1, W2t, b2, f, M_ALL, HID);

    // 5) prototypes + pp (fused, fp32 dot)
    protos_pp_k<<<WAYS, HID>>>(f, support_y, R1bT, R1b, ppb);

    // 6) q-half of R1
    gemm_k<false, false><<<dim3(8, Q_N / 128), 256, GEMM_SMEM>>>(f + (size_t)S_N * HID, R1tT, nullptr, qpb, Q_N, HID);

    // 7) fused relation GEMM (int8 IMMA) + R3 reduction + sigmoid
    relation_i8<<<Q_N * WAYS / 128, 256, REL_TOTAL>>>(qpb, ppb, R2i8, R2b, R3w, R3b, out);
}

// round 16
// speedup vs baseline: 1.0335x; 1.0335x over previous
#include <cuda_runtime.h>
#include <cuda_bf16.h>
#include <cstdint>
#include <math.h>

using bf16 = __nv_bfloat16;
#define DINLINE __device__ __forceinline__

// ---------------- problem dims ----------------
#define D_IN 1024
#define HID  512
#define WAYS 64
#define S_N  1024
#define Q_N  4096
#define M_ALL (S_N + Q_N)

// int8 quantization scales
#define SA_I 256.0f              // relation A = relu(qp+pp)
#define SB_I 1024.0f             // R2 weights
#define INV_SASB (1.0f / (256.0f * 1024.0f))
#define SX_I 32.0f               // encoder inputs
#define SW1_I 1024.0f            // W1 weights
#define INV_XW1 (1.0f / (32.0f * 1024.0f))

// ---------------- scratch (device globals; no allocation allowed) ----------------
__device__ __align__(256) signed char g_sx8[S_N * D_IN];
__device__ __align__(256) signed char g_qx8[Q_N * D_IN];
__device__ __align__(256) signed char g_W1t8[HID * D_IN];     // s8 [n][k]
__device__ __align__(256) bf16  g_W2t[HID * HID];
__device__ __align__(256) bf16  g_R1tT[HID * HID];            // R1w[:512] transposed
__device__ __align__(256) bf16  g_R1bT[HID * HID];            // R1w[512:] transposed
__device__ __align__(256) bf16  g_f1[M_ALL * HID];            // encoder layer1 out (S||Q)
__device__ __align__(256) bf16  g_f [M_ALL * HID];            // encoder layer2 out (S||Q)
__device__ __align__(256) bf16  g_protosb[WAYS * HID];
__device__ __align__(256) bf16  g_qpb[Q_N * HID];             // q-half of R1 output
__device__ __align__(256) bf16  g_ppb[WAYS * HID];            // proto-half of R1 + R1b
__device__ __align__(256) signed char g_R2i8[HID * HID];      // R2w^T int8 [n][k]

// ---------------- PTX helpers ----------------
DINLINE uint32_t smem_u32(const void* p) { return (uint32_t)__cvta_generic_to_shared(p); }

DINLINE void cp16(uint32_t saddr, const void* g) {
    asm volatile("cp.async.cg.shared.global [%0], [%1], 16;\n" :: "r"(saddr), "l"(g));
}
DINLINE void cp_commit() { asm volatile("cp.async.commit_group;\n"); }
DINLINE void cp_wait0()  { asm volatile("cp.async.wait_group 0;\n"); }
DINLINE void cp_wait1()  { asm volatile("cp.async.wait_group 1;\n"); }

DINLINE void ldmx4(uint32_t& r0, uint32_t& r1, uint32_t& r2, uint32_t& r3, uint32_t a) {
    asm volatile("ldmatrix.sync.aligned.m8n8.x4.shared.b16 {%0,%1,%2,%3}, [%4];\n"
                 : "=r"(r0), "=r"(r1), "=r"(r2), "=r"(r3) : "r"(a));
}
DINLINE void mma16816(float* c, uint32_t a0, uint32_t a1, uint32_t a2, uint32_t a3,
                      uint32_t b0, uint32_t b1) {
    asm volatile("mma.sync.aligned.m16n8k16.row.col.f32.bf16.bf16.f32 "
                 "{%0,%1,%2,%3}, {%4,%5,%6,%7}, {%8,%9}, {%0,%1,%2,%3};\n"
                 : "+f"(c[0]), "+f"(c[1]), "+f"(c[2]), "+f"(c[3])
                 : "r"(a0), "r"(a1), "r"(a2), "r"(a3), "r"(b0), "r"(b1));
}
DINLINE void mma16832_s8(int* c, uint32_t a0, uint32_t a1, uint32_t a2, uint32_t a3,
                         uint32_t b0, uint32_t b1) {
    asm volatile("mma.sync.aligned.m16n8k32.row.col.s32.s8.s8.s32 "
                 "{%0,%1,%2,%3}, {%4,%5,%6,%7}, {%8,%9}, {%0,%1,%2,%3};\n"
                 : "+r"(c[0]), "+r"(c[1]), "+r"(c[2]), "+r"(c[3])
                 : "r"(a0), "r"(a1), "r"(a2), "r"(a3), "r"(b0), "r"(b1));
}

DINLINE uint32_t pack_s8x4(int i0, int i1, int i2, int i3) {
    uint32_t t, d;
    asm("cvt.pack.sat.s8.s32.b32 %0, %1, %2, 0;" : "=r"(t) : "r"(i3), "r"(i2));
    asm("cvt.pack.sat.s8.s32.b32 %0, %1, %2, %3;" : "=r"(d) : "r"(i1), "r"(i0), "r"(t));
    return d;
}

DINLINE void unpk8(uint4 u, float* f) {
    __nv_bfloat162 h; float2 t;
    *(uint32_t*)&h = u.x; t = __bfloat1622float2(h); f[0] = t.x; f[1] = t.y;
    *(uint32_t*)&h = u.y; t = __bfloat1622float2(h); f[2] = t.x; f[3] = t.y;
    *(uint32_t*)&h = u.z; t = __bfloat1622float2(h); f[4] = t.x; f[5] = t.y;
    *(uint32_t*)&h = u.w; t = __bfloat1622float2(h); f[6] = t.x; f[7] = t.y;
}

// ---------------- consolidated prestage kernels ----------------
__global__ void quant2_s8(const float* __restrict__ sx, const float* __restrict__ qx,
                          signed char* __restrict__ sx8, signed char* __restrict__ qx8) {
    int i = (blockIdx.x * blockDim.x + threadIdx.x) * 4;
    const float* in;
    signed char* out;
    if (i < S_N * D_IN) { in = sx + i; out = sx8 + i; }
    else {
        int j = i - S_N * D_IN;
        if (j >= Q_N * D_IN) return;
        in = qx + j; out = qx8 + j;
    }
    float4 v = *(const float4*)in;
    uint32_t p = pack_s8x4(__float2int_rn(v.x * SX_I), __float2int_rn(v.y * SX_I),
                           __float2int_rn(v.z * SX_I), __float2int_rn(v.w * SX_I));
    *(uint32_t*)out = p;
}

// all 5 weight transposes in one launch; blockIdx.z selects the job.
__global__ void prep_weights(const float* __restrict__ W1, const float* __restrict__ W2,
                             const float* __restrict__ R1w, const float* __restrict__ R2w,
                             signed char* __restrict__ W1t8, bf16* __restrict__ W2t,
                             bf16* __restrict__ R1tT, bf16* __restrict__ R1bT,
                             signed char* __restrict__ R2i8) {
    __shared__ float t[32][33];
    const int z = blockIdx.z;
    const float* src; void* dst; int K, koff, mode; float scale;
    switch (z) {
        case 0:  src = W1;  dst = W1t8; K = D_IN; koff = 0;   mode = 1; scale = SW1_I; break;
        case 1:  src = W2;  dst = W2t;  K = HID;  koff = 0;   mode = 0; scale = 0.f;   break;
        case 2:  src = R1w; dst = R1tT; K = HID;  koff = 0;   mode = 0; scale = 0.f;   break;
        case 3:  src = R1w; dst = R1bT; K = HID;  koff = HID; mode = 0; scale = 0.f;   break;
        default: src = R2w; dst = R2i8; K = HID;  koff = 0;   mode = 1; scale = SB_I;  break;
    }
    const int kb = blockIdx.x * 32;
    if (kb >= K) return;
    const int nb = blockIdx.y * 32;
    const int tx = threadIdx.x & 31, ty = threadIdx.x >> 5;   // 32 x 8
#pragma unroll
    for (int r = 0; r < 4; r++)
        t[ty + r * 8][tx] = src[(size_t)(koff + kb + ty + r * 8) * HID + nb + tx];
    __syncthreads();
#pragma unroll
    for (int r = 0; r < 4; r++) {
        float v = t[tx][ty + r * 8];
        size_t o = (size_t)(nb + ty + r * 8) * K + kb + tx;
        if (mode == 0) ((bf16*)dst)[o] = __float2bfloat16(v);
        else {
            int i = __float2int_rn(v * scale);
            i = max(-127, min(127, i));
            ((signed char*)dst)[o] = (signed char)i;
        }
    }
}

// class prototypes (bf16 features): one block per class, 512 threads
__global__ void protos_k(const bf16* __restrict__ sf, const int* __restrict__ y,
                         bf16* __restrict__ pb) {
    __shared__ int ys[S_N];
    int w = blockIdx.x;
    for (int i = threadIdx.x; i < S_N; i += blockDim.x) ys[i] = y[i];
    __syncthreads();
    int h = threadIdx.x;
    float acc = 0.f;
    int cnt = 0;
    for (int s = 0; s < S_N; s++) {
        if (ys[s] == w) { acc += __bfloat162float(sf[(size_t)s * HID + h]); cnt++; }
    }
    float c = (float)(cnt > 0 ? cnt : 1);
    pb[(size_t)w * HID + h] = __float2bfloat16(acc / c);
}

// ---------------- generic bf16 TN GEMM (HMMA; pre-stages) ----------------
// BM=128, BN=64, 3-stage cp.async ring with ONE barrier per k-tile:
// the stage load for kt+2 is issued AFTER the iteration barrier, so any warp
// issuing it proves all warps completed iteration kt-1's reads of that buffer.
// (R13/R14 post-mortem: occupancy is at its 2-CTA cap; the limiter was the
// two __syncthreads per 64-wide k-tile serializing short compute bursts.)
template <bool BIAS, bool RELU>
__global__ void __launch_bounds__(256, 2) gemm_k(
    const bf16* __restrict__ A, const bf16* __restrict__ Bt,
    const float* __restrict__ bias, bf16* __restrict__ outB,
    int M, int K)
{
    extern __shared__ bf16 sm[];
    bf16* As = sm;                 // [3][128][72]
    bf16* Bs = sm + 3 * 9216;      // [3][64][72]
    const int tid = threadIdx.x;
    const int m0 = blockIdx.y * 128, n0 = blockIdx.x * 64;
    const int wid = tid >> 5, lane = tid & 31;
    const int wm = wid >> 1, wn = wid & 1;      // 4 M-warps x 2 N-warps
    const int grp = lane >> 2, tig = lane & 3;
    const uint32_t as_b = smem_u32(As), bs_b = smem_u32(Bs);

    auto load_tile = [&](int st, int kt) {
#pragma unroll
        for (int i = tid; i < 1536; i += 256) {
            if (i < 1024) {
                int r  = i >> 3;
                int ks = (i & 7) << 3;
                int ar = m0 + r; if (ar >= M) ar = M - 1;
                cp16(as_b + (uint32_t)(st * 9216 + r * 72 + ks) * 2,
                     A + (size_t)ar * K + kt * 64 + ks);
            } else {
                int j  = i - 1024;
                int r  = j >> 3;
                int ks = (j & 7) << 3;
                cp16(bs_b + (uint32_t)(st * 4608 + r * 72 + ks) * 2,
                     Bt + (size_t)(n0 + r) * K + kt * 64 + ks);
            }
        }
        cp_commit();
    };

    float c[2][4][4];
#pragma unroll
    for (int a = 0; a < 2; a++)
#pragma unroll
        for (int b = 0; b < 4; b++)
#pragma unroll
            for (int e = 0; e < 4; e++) c[a][b][e] = 0.f;

    const int KT = K >> 6;
    load_tile(0, 0);
    if (KT > 1) load_tile(1, 1);
    for (int kt = 0; kt < KT; kt++) {
        if (kt < KT - 1) cp_wait1(); else cp_wait0();
        __syncthreads();
        if (kt + 2 < KT) load_tile((kt + 2) % 3, kt + 2);
        const int st = kt % 3;
#pragma unroll
        for (int k16 = 0; k16 < 4; k16++) {
            uint32_t afr[2][4];
            uint32_t abase = as_b + (uint32_t)((st * 9216 + (wm * 32 + (lane & 15)) * 72
                                    + k16 * 16 + ((lane >> 4) << 3)) * 2);
#pragma unroll
            for (int ms = 0; ms < 2; ms++)
                ldmx4(afr[ms][0], afr[ms][1], afr[ms][2], afr[ms][3],
                      abase + (uint32_t)(ms * 16 * 72 * 2));
            uint32_t bfr[4][2];
#pragma unroll
            for (int ns = 0; ns < 4; ns++) {
                const bf16* p = Bs + st * 4608 + (wn * 32 + ns * 8 + grp) * 72
                                + k16 * 16 + 2 * tig;
                bfr[ns][0] = *(const uint32_t*)p;
                bfr[ns][1] = *(const uint32_t*)(p + 8);
            }
#pragma unroll
            for (int ms = 0; ms < 2; ms++)
#pragma unroll
                for (int ns = 0; ns < 4; ns++)
                    mma16816(c[ms][ns], afr[ms][0], afr[ms][1], afr[ms][2], afr[ms][3],
                             bfr[ns][0], bfr[ns][1]);
        }
    }

#pragma unroll
    for (int ms = 0; ms < 2; ms++) {
#pragma unroll
        for (int i = 0; i < 4; i++) {
            int row = m0 + wm * 32 + ms * 16 + grp + ((i >> 1) << 3);
            if (row < M) {
#pragma unroll
                for (int ns = 0; ns < 4; ns++) {
                    int col = n0 + wn * 32 + ns * 8 + tig * 2 + (i & 1);
                    float v = c[ms][ns][i];
                    if (BIAS) v += bias[col];
                    if (RELU) v = fmaxf(v, 0.f);
                    outB[(size_t)row * HID + col] = __float2bfloat16(v);
                }
            }
        }
    }
}

// ---------------- int8 GEMM: merged encoder layer 1 (support || query) ----------------
// BM=128, BN=64, same single-barrier 3-stage ring. M = 5120, grid 8x40=320.
#define G1A_STG 16384
#define G1B_OFF (3 * G1A_STG)
#define G1B_STRD 144
#define G1B_STG 9216
#define G1_TOTAL (G1B_OFF + 3 * G1B_STG)

__global__ void __launch_bounds__(256, 2) gemm1_i8(
    const signed char* __restrict__ Asup, const signed char* __restrict__ Aqry,
    const signed char* __restrict__ B8,
    const float* __restrict__ bias, bf16* __restrict__ outB)
{
    extern __shared__ __align__(128) char sm8[];
    char* As = sm8;
    char* Bs = sm8 + G1B_OFF;
    const int tid = threadIdx.x;
    const int wid = tid >> 5, lane = tid & 31;
    const int wm = wid >> 1, wn = wid & 1;      // 4 M-warps x 2 N-warps
    const int grp = lane >> 2, tig = lane & 3;
    const int m0 = blockIdx.y * 128, n0 = blockIdx.x * 64;
    const signed char* A8 = (m0 < S_N) ? (Asup + (size_t)m0 * D_IN)
                                       : (Aqry + (size_t)(m0 - S_N) * D_IN);
    const uint32_t as_b = smem_u32(As), bs_b = smem_u32(Bs);

    auto load_tile = [&](int st, int kt) {
#pragma unroll
        for (int j = 0; j < 4; j++) {
            int idx = j * 256 + tid;
            int r = idx >> 3, c = idx & 7;
            cp16(as_b + (uint32_t)(st * G1A_STG + r * 128 + (((c ^ r) & 7) << 4)),
                 A8 + (size_t)r * D_IN + kt * 128 + c * 16);
        }
#pragma unroll
        for (int j = 0; j < 2; j++) {
            int idx = j * 256 + tid;
            int r = idx >> 3, c = idx & 7;
            cp16(bs_b + (uint32_t)(st * G1B_STG + r * G1B_STRD + c * 16),
                 B8 + (size_t)(n0 + r) * D_IN + kt * 128 + c * 16);
        }
        cp_commit();
    };

    int ci[2][4][4];
#pragma unroll
    for (int a = 0; a < 2; a++)
#pragma unroll
        for (int b = 0; b < 4; b++)
#pragma unroll
            for (int e = 0; e < 4; e++) ci[a][b][e] = 0;

    load_tile(0, 0);
    load_tile(1, 1);
    for (int kt = 0; kt < 8; kt++) {
        if (kt < 7) cp_wait1(); else cp_wait0();
        __syncthreads();
        if (kt + 2 < 8) load_tile((kt + 2) % 3, kt + 2);
        const int st = kt % 3;
#pragma unroll
        for (int k32 = 0; k32 < 4; k32++) {
            uint32_t afr[2][4];
            {
                const int arow0 = wm * 32 + (lane & 15);
                const int achk  = k32 * 2 + (lane >> 4);
#pragma unroll
                for (int ms = 0; ms < 2; ms++) {
                    const int arow = arow0 + ms * 16;
                    uint32_t aaddr = as_b + (uint32_t)(st * G1A_STG + arow * 128
                                   + (((achk ^ arow) & 7) << 4));
                    ldmx4(afr[ms][0], afr[ms][1], afr[ms][2], afr[ms][3], aaddr);
                }
            }
            uint32_t bfr[4][2];
#pragma unroll
            for (int ns = 0; ns < 4; ns++) {
                const char* p = Bs + st * G1B_STG
                              + (wn * 32 + ns * 8 + grp) * G1B_STRD
                              + k32 * 32 + tig * 4;
                bfr[ns][0] = *(const uint32_t*)p;
                bfr[ns][1] = *(const uint32_t*)(p + 16);
            }
#pragma unroll
            for (int ms = 0; ms < 2; ms++)
#pragma unroll
                for (int ns = 0; ns < 4; ns++)
                    mma16832_s8(ci[ms][ns], afr[ms][0], afr[ms][1], afr[ms][2], afr[ms][3],
                                bfr[ns][0], bfr[ns][1]);
        }
    }

#pragma unroll
    for (int ms = 0; ms < 2; ms++) {
#pragma unroll
        for (int i = 0; i < 4; i++) {
            int row = m0 + wm * 32 + ms * 16 + grp + ((i >> 1) << 3);
#pragma unroll
            for (int ns = 0; ns < 4; ns++) {
                int col = n0 + wn * 32 + ns * 8 + tig * 2 + (i & 1);
                float v = (float)ci[ms][ns][i] * INV_XW1 + bias[col];
                v = fmaxf(v, 0.f);
                outB[(size_t)row * HID + col] = __float2bfloat16(v);
            }
        }
    }
}

// ---------------- int8 fused relation kernel (unchanged — R7 win) ----------------
#define RELA_OFF   0
#define RELB_OFF   65536
#define RELB_STG   18432
#define RELB_STRD  144
#define RELR2B_OFF 102400
#define RELR3W_OFF 104448
#define RELRED_OFF 106496
#define REL_TOTAL  108544

__global__ void __launch_bounds__(256, 2) relation_i8(
    const bf16* __restrict__ qpb, const bf16* __restrict__ ppb,
    const signed char* __restrict__ Bi8,
    const float* __restrict__ R2b, const float* __restrict__ R3w,
    const float* __restrict__ R3b, float* __restrict__ out)
{
    extern __shared__ __align__(128) char sm8[];
    char*  As8  = sm8 + RELA_OFF;
    char*  Bs8  = sm8 + RELB_OFF;
    float* sR2b = (float*)(sm8 + RELR2B_OFF);
    float* sR3w = (float*)(sm8 + RELR3W_OFF);
    float* red  = (float*)(sm8 + RELRED_OFF);
    const uint32_t as_b = smem_u32(As8);
    const uint32_t bs_b = smem_u32(Bs8);
    const int tid = threadIdx.x;
    const int wid = tid >> 5, lane = tid & 31;
    const int wm = wid >> 2, wn = wid & 3;
    const int grp = lane >> 2, tig = lane & 3;
    const int q0 = blockIdx.x * 2;

    auto loadB = [&](int flat) {
        int st = flat & 1, p = flat >> 2, kt = flat & 3;
#pragma unroll
        for (int j = 0; j < 4; j++) {
            int idx = j * 256 + tid;
            int r = idx >> 3, cc = idx & 7;
            cp16(bs_b + (uint32_t)(st * RELB_STG + r * RELB_STRD + cc * 16),
                 Bi8 + (size_t)(p * 128 + r) * HID + kt * 128 + cc * 16);
        }
        cp_commit();
    };

    loadB(0);

    for (int i = tid; i < HID; i += 256) { sR2b[i] = R2b[i]; sR3w[i] = R3w[i]; }

    // ---- build A: As[row][k] = sat_s8(relu(qp[q][k]+pp[w][k]) * SA_I), swizzled ----
    {
        const int c = tid & 31;
        const int wg = tid >> 5;
        float qv[2][16];
#pragma unroll
        for (int qi = 0; qi < 2; qi++) {
            const bf16* p = qpb + (size_t)(q0 + qi) * HID + c * 16;
            unpk8(*(const uint4*)p, qv[qi]);
            unpk8(*(const uint4*)(p + 8), qv[qi] + 8);
        }
        for (int w = wg * 8; w < wg * 8 + 8; w++) {
            float pv[16];
            const bf16* p = ppb + (size_t)w * HID + c * 16;
            unpk8(*(const uint4*)p, pv);
            unpk8(*(const uint4*)(p + 8), pv + 8);
#pragma unroll
            for (int qi = 0; qi < 2; qi++) {
                int row = qi * 64 + w;
                uint32_t pk[4];
#pragma unroll
                for (int g = 0; g < 4; g++) {
                    int ii[4];
#pragma unroll
                    for (int e = 0; e < 4; e++) {
                        float f = fmaxf(qv[qi][g * 4 + e] + pv[g * 4 + e], 0.f) * SA_I;
                        ii[e] = __float2int_rn(f);
                    }
                    pk[g] = pack_s8x4(ii[0], ii[1], ii[2], ii[3]);
                }
                uint32_t off = (uint32_t)(row * 512 + ((c >> 3) << 7) + (((c ^ row) & 7) << 4));
                *(uint4*)(As8 + off) = make_uint4(pk[0], pk[1], pk[2], pk[3]);
            }
        }
    }

    float rp[8];
#pragma unroll
    for (int j = 0; j < 8; j++) rp[j] = 0.f;

    for (int pass = 0; pass < 4; pass++) {
        const int n0 = pass * 128;
        int ci[4][4][4];
#pragma unroll
        for (int a = 0; a < 4; a++)
#pragma unroll
            for (int b = 0; b < 4; b++)
#pragma unroll
                for (int e = 0; e < 4; e++) ci[a][b][e] = 0;

        for (int kt = 0; kt < 4; kt++) {
            const int flat = pass * 4 + kt;
            if (flat + 1 < 16) { loadB(flat + 1); cp_wait1(); }
            else               { cp_wait0(); }
            __syncthreads();
            const int st = flat & 1;
#pragma unroll
            for (int k32 = 0; k32 < 4; k32++) {
                const int cbase = kt * 8 + k32 * 2;
                uint32_t afr[4][4];
                {
                    const int arow0 = wm * 64 + (lane & 15);
                    const int achk  = cbase + (lane >> 4);
#pragma unroll
                    for (int ms = 0; ms < 4; ms++) {
                        const int arow = arow0 + ms * 16;
                        uint32_t aaddr = as_b + (uint32_t)(arow * 512 + ((achk >> 3) << 7)
                                       + (((achk ^ arow) & 7) << 4));
                        ldmx4(afr[ms][0], afr[ms][1], afr[ms][2], afr[ms][3], aaddr);
                    }
                }
                uint32_t bfr[4][2];
#pragma unroll
                for (int ns = 0; ns < 4; ns++) {
                    const char* p = Bs8 + st * RELB_STG
                                  + (wn * 32 + ns * 8 + grp) * RELB_STRD
                                  + k32 * 32 + tig * 4;
                    bfr[ns][0] = *(const uint32_t*)p;
                    bfr[ns][1] = *(const uint32_t*)(p + 16);
                }
#pragma unroll
                for (int ms = 0; ms < 4; ms++)
#pragma unroll
                    for (int ns = 0; ns < 4; ns++)
                        mma16832_s8(ci[ms][ns], afr[ms][0], afr[ms][1], afr[ms][2], afr[ms][3],
                                    bfr[ns][0], bfr[ns][1]);
            }
            __syncthreads();
        }

#pragma unroll
        for (int ns = 0; ns < 4; ns++) {
            int colbase = n0 + wn * 32 + ns * 8 + tig * 2;
            float bb0 = sR2b[colbase], bb1 = sR2b[colbase + 1];
            float w0 = sR3w[colbase],  w1 = sR3w[colbase + 1];
#pragma unroll
            for (int ms = 0; ms < 4; ms++) {
                rp[ms * 2 + 0] += fmaxf((float)ci[ms][ns][0] * INV_SASB + bb0, 0.f) * w0
                                + fmaxf((float)ci[ms][ns][1] * INV_SASB + bb1, 0.f) * w1;
                rp[ms * 2 + 1] += fmaxf((float)ci[ms][ns][2] * INV_SASB + bb0, 0.f) * w0
                                + fmaxf((float)ci[ms][ns][3] * INV_SASB + bb1, 0.f) * w1;
            }
        }
    }

#pragma unroll
    for (int j = 0; j < 8; j++) {
        rp[j] += __shfl_xor_sync(0xffffffffu, rp[j], 1);
        rp[j] += __shfl_xor_sync(0xffffffffu, rp[j], 2);
    }
    if (tig == 0) {
#pragma unroll
        for (int j = 0; j < 8; j++) {
            int row = wm * 64 + (j >> 1) * 16 + grp + (j & 1) * 8;
            red[row * 4 + wn] = rp[j];
        }
    }
    __syncthreads();
    if (tid < 128) {
        float s = red[tid * 4 + 0] + red[tid * 4 + 1] + red[tid * 4 + 2] + red[tid * 4 + 3]
                + R3b[0];
        out[(size_t)blockIdx.x * 128 + tid] = 1.f / (1.f + expf(-s));
    }
}

// ---------------- host launcher ----------------
extern "C" void kernel_launch(void* const* d_in, const int* in_sizes, int n_in,
                              void* d_out, int out_size)
{
    (void)in_sizes; (void)n_in; (void)out_size;
    const float* support_x = (const float*)d_in[0];
    const int*   support_y = (const int*)d_in[1];
    const float* query_x   = (const float*)d_in[2];
    const float* W1  = (const float*)d_in[3];
    const float* b1  = (const float*)d_in[4];
    const float* W2  = (const float*)d_in[5];
    const float* b2  = (const float*)d_in[6];
    const float* R1w = (const float*)d_in[7];
    const float* R1b = (const float*)d_in[8];
    const float* R2w = (const float*)d_in[9];
    const float* R2b = (const float*)d_in[10];
    const float* R3w = (const float*)d_in[11];
    const float* R3b = (const float*)d_in[12];
    float* out = (float*)d_out;

    bf16 *W2t, *R1tT, *R1bT, *f1, *f, *protosb, *qpb, *ppb;
    signed char *R2i8, *sx8, *qx8, *W1t8;
    cudaGetSymbolAddress((void**)&sx8, g_sx8);
    cudaGetSymbolAddress((void**)&qx8, g_qx8);
    cudaGetSymbolAddress((void**)&W1t8, g_W1t8);
    cudaGetSymbolAddress((void**)&W2t, g_W2t);
    cudaGetSymbolAddress((void**)&R1tT, g_R1tT);
    cudaGetSymbolAddress((void**)&R1bT, g_R1bT);
    cudaGetSymbolAddress((void**)&f1, g_f1);
    cudaGetSymbolAddress((void**)&f,  g_f);
    cudaGetSymbolAddress((void**)&protosb, g_protosb);
    cudaGetSymbolAddress((void**)&qpb, g_qpb);
    cudaGetSymbolAddress((void**)&ppb, g_ppb);
    cudaGetSymbolAddress((void**)&R2i8, g_R2i8);

    const int GEMM_SMEM = 3 * (9216 + 4608) * 2;  // 82944 B
    cudaFuncSetAttribute(gemm_k<true,  true >, cudaFuncAttributeMaxDynamicSharedMemorySize, GEMM_SMEM);
    cudaFuncSetAttribute(gemm_k<true,  false>, cudaFuncAttributeMaxDynamicSharedMemorySize, GEMM_SMEM);
    cudaFuncSetAttribute(gemm_k<false, false>, cudaFuncAttributeMaxDynamicSharedMemorySize, GEMM_SMEM);
    cudaFuncSetAttribute(gemm1_i8, cudaFuncAttributeMaxDynamicSharedMemorySize, G1_TOTAL);
    cudaFuncSetAttribute(relation_i8, cudaFuncAttributeMaxDynamicSharedMemorySize, REL_TOTAL);

    // 1) quantize both inputs (one launch)
    quant2_s8<<<(M_ALL * D_IN / 4 + 255) / 256, 256>>>(support_x, query_x, sx8, qx8);

    // 2) all weight transposes (one launch)
    prep_weights<<<dim3(32, 16, 5), 256>>>(W1, W2, R1w, R2w, W1t8, W2t, R1tT, R1bT, R2i8);

    // 3) merged encoder layer 1 (int8, S || Q)
    gemm1_i8<<<dim3(8, M_ALL / 128), 256, G1_TOTAL>>>(sx8, qx8, W1t8, b1, f1);

    // 4) merged encoder layer 2 (bf16, S || Q)
    gemm_k<true, true><<<dim3(8, M_ALL / 128), 256, GEMM_SMEM>>>(f1, W2t, b2, f, M_ALL, HID);

    // 5) prototypes (from bf16 support features)
    protos_k<<<WAYS, HID>>>(f, support_y, protosb);

    // 6) relation first-layer halves (pp via tensor GEMM, qp via gemm_k)
    gemm_k<true,  false><<<dim3(8, 1),         256, GEMM_SMEM>>>(protosb, R1bT, R1b, ppb, WAYS, HID);
    gemm_k<false, false><<<dim3(8, Q_N / 128), 256, GEMM_SMEM>>>(f + (size_t)S_N * HID, R1tT, nullptr, qpb, Q_N, HID);

    // 7) fused relation GEMM (int8 IMMA) + R3 reduction + sigmoid
    relation_i8<<<Q_N * WAYS / 128, 256, REL_TOTAL>>>(qpb, ppb, R2i8, R2b, R3w, R3b, out);
}

// round 17
// speedup vs baseline: 1.0649x; 1.0304x over previous
#include <cuda_runtime.h>
#include <cuda_bf16.h>
#include <cstdint>
#include <math.h>

using bf16 = __nv_bfloat16;
#define DINLINE __device__ __forceinline__

// ---------------- problem dims ----------------
#define D_IN 1024
#define HID  512
#define WAYS 64
#define S_N  1024
#define Q_N  4096
#define M_ALL (S_N + Q_N)

// int8 quantization scales
#define SA_I 256.0f                      // relation A = relu(qp+pp)
#define SB_I 1024.0f                     // R2 weights
#define INV_SASB (1.0f / (256.0f * 1024.0f))
#define SX_I 32.0f                       // encoder inputs
#define SW_I 1024.0f                     // all weight int8 scales
#define SF1_I 32.0f                      // f1 activations (std ~0.45, sat 3.97)
#define SF_I  64.0f                      // f  activations (std ~0.2,  sat 1.98)
#define DQ1 (1.0f / (32.0f * 1024.0f))   // enc1 dequant (x*W1)
#define DQ2 (1.0f / (32.0f * 1024.0f))   // enc2 dequant (f1*W2)
#define DQQ (1.0f / (64.0f * 1024.0f))   // qp dequant (f*R1t)

// ---------------- scratch (device globals; no allocation allowed) ----------------
__device__ __align__(256) signed char g_sx8[S_N * D_IN];
__device__ __align__(256) signed char g_qx8[Q_N * D_IN];
__device__ __align__(256) signed char g_W1t8[HID * D_IN];     // s8 [n][k]
__device__ __align__(256) signed char g_W2t8[HID * HID];      // s8 [n][k]
__device__ __align__(256) signed char g_R1t8[HID * HID];      // R1w[:512]^T s8
__device__ __align__(256) bf16  g_R1bT[HID * HID];            // R1w[512:]^T bf16
__device__ __align__(256) signed char g_f1_8[M_ALL * HID];    // enc1 out, s8 (scale 32)
__device__ __align__(256) bf16  g_f [M_ALL * HID];            // enc2 out, bf16
__device__ __align__(256) signed char g_f8[M_ALL * HID];      // enc2 out, s8 (scale 64)
__device__ __align__(256) bf16  g_protosb[WAYS * HID];
__device__ __align__(256) bf16  g_qpb[Q_N * HID];             // q-half of R1 output
__device__ __align__(256) bf16  g_ppb[WAYS * HID];            // proto-half of R1 + R1b
__device__ __align__(256) signed char g_R2i8[HID * HID];      // R2w^T int8 [n][k]

// ---------------- PTX helpers ----------------
DINLINE uint32_t smem_u32(const void* p) { return (uint32_t)__cvta_generic_to_shared(p); }

DINLINE void cp16(uint32_t saddr, const void* g) {
    asm volatile("cp.async.cg.shared.global [%0], [%1], 16;\n" :: "r"(saddr), "l"(g));
}
DINLINE void cp_commit() { asm volatile("cp.async.commit_group;\n"); }
DINLINE void cp_wait0()  { asm volatile("cp.async.wait_group 0;\n"); }
DINLINE void cp_wait1()  { asm volatile("cp.async.wait_group 1;\n"); }

DINLINE void ldmx4(uint32_t& r0, uint32_t& r1, uint32_t& r2, uint32_t& r3, uint32_t a) {
    asm volatile("ldmatrix.sync.aligned.m8n8.x4.shared.b16 {%0,%1,%2,%3}, [%4];\n"
                 : "=r"(r0), "=r"(r1), "=r"(r2), "=r"(r3) : "r"(a));
}
DINLINE void mma16816(float* c, uint32_t a0, uint32_t a1, uint32_t a2, uint32_t a3,
                      uint32_t b0, uint32_t b1) {
    asm volatile("mma.sync.aligned.m16n8k16.row.col.f32.bf16.bf16.f32 "
                 "{%0,%1,%2,%3}, {%4,%5,%6,%7}, {%8,%9}, {%0,%1,%2,%3};\n"
                 : "+f"(c[0]), "+f"(c[1]), "+f"(c[2]), "+f"(c[3])
                 : "r"(a0), "r"(a1), "r"(a2), "r"(a3), "r"(b0), "r"(b1));
}
DINLINE void mma16832_s8(int* c, uint32_t a0, uint32_t a1, uint32_t a2, uint32_t a3,
                         uint32_t b0, uint32_t b1) {
    asm volatile("mma.sync.aligned.m16n8k32.row.col.s32.s8.s8.s32 "
                 "{%0,%1,%2,%3}, {%4,%5,%6,%7}, {%8,%9}, {%0,%1,%2,%3};\n"
                 : "+r"(c[0]), "+r"(c[1]), "+r"(c[2]), "+r"(c[3])
                 : "r"(a0), "r"(a1), "r"(a2), "r"(a3), "r"(b0), "r"(b1));
}

DINLINE uint32_t pack_s8x4(int i0, int i1, int i2, int i3) {
    uint32_t t, d;
    asm("cvt.pack.sat.s8.s32.b32 %0, %1, %2, 0;" : "=r"(t) : "r"(i3), "r"(i2));
    asm("cvt.pack.sat.s8.s32.b32 %0, %1, %2, %3;" : "=r"(d) : "r"(i1), "r"(i0), "r"(t));
    return d;
}
DINLINE signed char sat8f(float v) {
    int i = __float2int_rn(v);
    i = max(-127, min(127, i));
    return (signed char)i;
}

DINLINE void unpk8(uint4 u, float* f) {
    __nv_bfloat162 h; float2 t;
    *(uint32_t*)&h = u.x; t = __bfloat1622float2(h); f[0] = t.x; f[1] = t.y;
    *(uint32_t*)&h = u.y; t = __bfloat1622float2(h); f[2] = t.x; f[3] = t.y;
    *(uint32_t*)&h = u.z; t = __bfloat1622float2(h); f[4] = t.x; f[5] = t.y;
    *(uint32_t*)&h = u.w; t = __bfloat1622float2(h); f[6] = t.x; f[7] = t.y;
}

// ---------------- consolidated prestage kernels ----------------
__global__ void quant2_s8(const float* __restrict__ sx, const float* __restrict__ qx,
                          signed char* __restrict__ sx8, signed char* __restrict__ qx8) {
    int i = (blockIdx.x * blockDim.x + threadIdx.x) * 4;
    const float* in;
    signed char* out;
    if (i < S_N * D_IN) { in = sx + i; out = sx8 + i; }
    else {
        int j = i - S_N * D_IN;
        if (j >= Q_N * D_IN) return;
        in = qx + j; out = qx8 + j;
    }
    float4 v = *(const float4*)in;
    uint32_t p = pack_s8x4(__float2int_rn(v.x * SX_I), __float2int_rn(v.y * SX_I),
                           __float2int_rn(v.z * SX_I), __float2int_rn(v.w * SX_I));
    *(uint32_t*)out = p;
}

// all 5 weight transposes in one launch; blockIdx.z selects the job.
__global__ void prep_weights(const float* __restrict__ W1, const float* __restrict__ W2,
                             const float* __restrict__ R1w, const float* __restrict__ R2w,
                             signed char* __restrict__ W1t8, signed char* __restrict__ W2t8,
                             signed char* __restrict__ R1t8, bf16* __restrict__ R1bT,
                             signed char* __restrict__ R2i8) {
    __shared__ float t[32][33];
    const int z = blockIdx.z;
    const float* src; void* dst; int K, koff, mode;
    switch (z) {
        case 0:  src = W1;  dst = W1t8; K = D_IN; koff = 0;   mode = 1; break;
        case 1:  src = W2;  dst = W2t8; K = HID;  koff = 0;   mode = 1; break;
        case 2:  src = R1w; dst = R1t8; K = HID;  koff = 0;   mode = 1; break;
        case 3:  src = R1w; dst = R1bT; K = HID;  koff = HID; mode = 0; break;
        default: src = R2w; dst = R2i8; K = HID;  koff = 0;   mode = 1; break;
    }
    const int kb = blockIdx.x * 32;
    if (kb >= K) return;
    const int nb = blockIdx.y * 32;
    const int tx = threadIdx.x & 31, ty = threadIdx.x >> 5;   // 32 x 8
#pragma unroll
    for (int r = 0; r < 4; r++)
        t[ty + r * 8][tx] = src[(size_t)(koff + kb + ty + r * 8) * HID + nb + tx];
    __syncthreads();
#pragma unroll
    for (int r = 0; r < 4; r++) {
        float v = t[tx][ty + r * 8];
        size_t o = (size_t)(nb + ty + r * 8) * K + kb + tx;
        if (mode == 0) ((bf16*)dst)[o] = __float2bfloat16(v);
        else           ((signed char*)dst)[o] = sat8f(v * SW_I);
    }
}

// class prototypes (bf16 features): one block per class, 512 threads
__global__ void protos_k(const bf16* __restrict__ sf, const int* __restrict__ y,
                         bf16* __restrict__ pb) {
    __shared__ int ys[S_N];
    int w = blockIdx.x;
    for (int i = threadIdx.x; i < S_N; i += blockDim.x) ys[i] = y[i];
    __syncthreads();
    int h = threadIdx.x;
    float acc = 0.f;
    int cnt = 0;
    for (int s = 0; s < S_N; s++) {
        if (ys[s] == w) { acc += __bfloat162float(sf[(size_t)s * HID + h]); cnt++; }
    }
    float c = (float)(cnt > 0 ? cnt : 1);
    pb[(size_t)w * HID + h] = __float2bfloat16(acc / c);
}

// ---------------- bf16 TN GEMM (only the tiny pp launch uses it) ----------------
template <bool BIAS, bool RELU>
__global__ void __launch_bounds__(256, 2) gemm_k(
    const bf16* __restrict__ A, const bf16* __restrict__ Bt,
    const float* __restrict__ bias, bf16* __restrict__ outB,
    int M, int K)
{
    extern __shared__ bf16 sm[];
    bf16* As = sm;                 // [3][128][72]
    bf16* Bs = sm + 3 * 9216;      // [3][64][72]
    const int tid = threadIdx.x;
    const int m0 = blockIdx.y * 128, n0 = blockIdx.x * 64;
    const int wid = tid >> 5, lane = tid & 31;
    const int wm = wid >> 1, wn = wid & 1;
    const int grp = lane >> 2, tig = lane & 3;
    const uint32_t as_b = smem_u32(As), bs_b = smem_u32(Bs);

    auto load_tile = [&](int st, int kt) {
#pragma unroll
        for (int i = tid; i < 1536; i += 256) {
            if (i < 1024) {
                int r  = i >> 3;
                int ks = (i & 7) << 3;
                int ar = m0 + r; if (ar >= M) ar = M - 1;
                cp16(as_b + (uint32_t)(st * 9216 + r * 72 + ks) * 2,
                     A + (size_t)ar * K + kt * 64 + ks);
            } else {
                int j  = i - 1024;
                int r  = j >> 3;
                int ks = (j & 7) << 3;
                cp16(bs_b + (uint32_t)(st * 4608 + r * 72 + ks) * 2,
                     Bt + (size_t)(n0 + r) * K + kt * 64 + ks);
            }
        }
        cp_commit();
    };

    float c[2][4][4];
#pragma unroll
    for (int a = 0; a < 2; a++)
#pragma unroll
        for (int b = 0; b < 4; b++)
#pragma unroll
            for (int e = 0; e < 4; e++) c[a][b][e] = 0.f;

    const int KT = K >> 6;
    load_tile(0, 0);
    if (KT > 1) load_tile(1, 1);
    for (int kt = 0; kt < KT; kt++) {
        if (kt < KT - 1) cp_wait1(); else cp_wait0();
        __syncthreads();
        if (kt + 2 < KT) load_tile((kt + 2) % 3, kt + 2);
        const int st = kt % 3;
#pragma unroll
        for (int k16 = 0; k16 < 4; k16++) {
            uint32_t afr[2][4];
            uint32_t abase = as_b + (uint32_t)((st * 9216 + (wm * 32 + (lane & 15)) * 72
                                    + k16 * 16 + ((lane >> 4) << 3)) * 2);
#pragma unroll
            for (int ms = 0; ms < 2; ms++)
                ldmx4(afr[ms][0], afr[ms][1], afr[ms][2], afr[ms][3],
                      abase + (uint32_t)(ms * 16 * 72 * 2));
            uint32_t bfr[4][2];
#pragma unroll
            for (int ns = 0; ns < 4; ns++) {
                const bf16* p = Bs + st * 4608 + (wn * 32 + ns * 8 + grp) * 72
                                + k16 * 16 + 2 * tig;
                bfr[ns][0] = *(const uint32_t*)p;
                bfr[ns][1] = *(const uint32_t*)(p + 8);
            }
#pragma unroll
            for (int ms = 0; ms < 2; ms++)
#pragma unroll
                for (int ns = 0; ns < 4; ns++)
                    mma16816(c[ms][ns], afr[ms][0], afr[ms][1], afr[ms][2], afr[ms][3],
                             bfr[ns][0], bfr[ns][1]);
        }
    }

#pragma unroll
    for (int ms = 0; ms < 2; ms++) {
#pragma unroll
        for (int i = 0; i < 4; i++) {
            int row = m0 + wm * 32 + ms * 16 + grp + ((i >> 1) << 3);
            if (row < M) {
#pragma unroll
                for (int ns = 0; ns < 4; ns++) {
                    int col = n0 + wn * 32 + ns * 8 + tig * 2 + (i & 1);
                    float v = c[ms][ns][i];
                    if (BIAS) v += bias[col];
                    if (RELU) v = fmaxf(v, 0.f);
                    outB[(size_t)row * HID + col] = __float2bfloat16(v);
                }
            }
        }
    }
}

// ---------------- unified int8 TN GEMM ----------------
// BM=128, BN=64, K = KT*128, 3-stage single-barrier cp.async ring.
// SPLIT: A = Asup rows [0,S_N) then Aqry. Epilogue: dq + optional bias/relu,
// then optional bf16 store (outB) and/or int8 store (out8 at oscale).
#define GIA_STG 16384
#define GIB_OFF (3 * GIA_STG)
#define GIB_STRD 144
#define GIB_STG 9216
#define GI_TOTAL (GIB_OFF + 3 * GIB_STG)

template <int KT, bool SPLIT, bool BIAS, bool RELU, bool OUTB, bool OUT8>
__global__ void __launch_bounds__(256, 2) gemm_i8(
    const signed char* __restrict__ Asup, const signed char* __restrict__ Aqry,
    const signed char* __restrict__ B8, const float* __restrict__ bias,
    float dq, float oscale,
    bf16* __restrict__ outB, signed char* __restrict__ out8)
{
    constexpr int K = KT * 128;
    extern __shared__ __align__(128) char sm8[];
    char* As = sm8;
    char* Bs = sm8 + GIB_OFF;
    const int tid = threadIdx.x;
    const int wid = tid >> 5, lane = tid & 31;
    const int wm = wid >> 1, wn = wid & 1;      // 4 M-warps x 2 N-warps
    const int grp = lane >> 2, tig = lane & 3;
    const int m0 = blockIdx.y * 128, n0 = blockIdx.x * 64;
    const signed char* A8;
    if (SPLIT) A8 = (m0 < S_N) ? (Asup + (size_t)m0 * K)
                               : (Aqry + (size_t)(m0 - S_N) * K);
    else       A8 = Asup + (size_t)m0 * K;
    const uint32_t as_b = smem_u32(As), bs_b = smem_u32(Bs);

    auto load_tile = [&](int st, int kt) {
#pragma unroll
        for (int j = 0; j < 4; j++) {
            int idx = j * 256 + tid;
            int r = idx >> 3, c = idx & 7;
            cp16(as_b + (uint32_t)(st * GIA_STG + r * 128 + (((c ^ r) & 7) << 4)),
                 A8 + (size_t)r * K + kt * 128 + c * 16);
        }
#pragma unroll
        for (int j = 0; j < 2; j++) {
            int idx = j * 256 + tid;
            int r = idx >> 3, c = idx & 7;
            cp16(bs_b + (uint32_t)(st * GIB_STG + r * GIB_STRD + c * 16),
                 B8 + (size_t)(n0 + r) * K + kt * 128 + c * 16);
        }
        cp_commit();
    };

    int ci[2][4][4];
#pragma unroll
    for (int a = 0; a < 2; a++)
#pragma unroll
        for (int b = 0; b < 4; b++)
#pragma unroll
            for (int e = 0; e < 4; e++) ci[a][b][e] = 0;

    load_tile(0, 0);
    if (KT > 1) load_tile(1, 1);
    for (int kt = 0; kt < KT; kt++) {
        if (kt < KT - 1) cp_wait1(); else cp_wait0();
        __syncthreads();
        if (kt + 2 < KT) load_tile((kt + 2) % 3, kt + 2);
        const int st = kt % 3;
#pragma unroll
        for (int k32 = 0; k32 < 4; k32++) {
            uint32_t afr[2][4];
            {
                const int arow0 = wm * 32 + (lane & 15);
                const int achk  = k32 * 2 + (lane >> 4);
#pragma unroll
                for (int ms = 0; ms < 2; ms++) {
                    const int arow = arow0 + ms * 16;
                    uint32_t aaddr = as_b + (uint32_t)(st * GIA_STG + arow * 128
                                   + (((achk ^ arow) & 7) << 4));
                    ldmx4(afr[ms][0], afr[ms][1], afr[ms][2], afr[ms][3], aaddr);
                }
            }
            uint32_t bfr[4][2];
#pragma unroll
            for (int ns = 0; ns < 4; ns++) {
                const char* p = Bs + st * GIB_STG
                              + (wn * 32 + ns * 8 + grp) * GIB_STRD
                              + k32 * 32 + tig * 4;
                bfr[ns][0] = *(const uint32_t*)p;
                bfr[ns][1] = *(const uint32_t*)(p + 16);
            }
#pragma unroll
            for (int ms = 0; ms < 2; ms++)
#pragma unroll
                for (int ns = 0; ns < 4; ns++)
                    mma16832_s8(ci[ms][ns], afr[ms][0], afr[ms][1], afr[ms][2], afr[ms][3],
                                bfr[ns][0], bfr[ns][1]);
        }
    }

#pragma unroll
    for (int ms = 0; ms < 2; ms++) {
#pragma unroll
        for (int i = 0; i < 4; i++) {
            int row = m0 + wm * 32 + ms * 16 + grp + ((i >> 1) << 3);
#pragma unroll
            for (int ns = 0; ns < 4; ns++) {
                int col = n0 + wn * 32 + ns * 8 + tig * 2 + (i & 1);
                float v = (float)ci[ms][ns][i] * dq;
                if (BIAS) v += bias[col];
                if (RELU) v = fmaxf(v, 0.f);
                if (OUTB) outB[(size_t)row * HID + col] = __float2bfloat16(v);
                if (OUT8) out8[(size_t)row * HID + col] = sat8f(v * oscale);
            }
        }
    }
}

// ---------------- int8 fused relation kernel (unchanged — R7 win) ----------------
#define RELA_OFF   0
#define RELB_OFF   65536
#define RELB_STG   18432
#define RELB_STRD  144
#define RELR2B_OFF 102400
#define RELR3W_OFF 104448
#define RELRED_OFF 106496
#define REL_TOTAL  108544

__global__ void __launch_bounds__(256, 2) relation_i8(
    const bf16* __restrict__ qpb, const bf16* __restrict__ ppb,
    const signed char* __restrict__ Bi8,
    const float* __restrict__ R2b, const float* __restrict__ R3w,
    const float* __restrict__ R3b, float* __restrict__ out)
{
    extern __shared__ __align__(128) char sm8[];
    char*  As8  = sm8 + RELA_OFF;
    char*  Bs8  = sm8 + RELB_OFF;
    float* sR2b = (float*)(sm8 + RELR2B_OFF);
    float* sR3w = (float*)(sm8 + RELR3W_OFF);
    float* red  = (float*)(sm8 + RELRED_OFF);
    const uint32_t as_b = smem_u32(As8);
    const uint32_t bs_b = smem_u32(Bs8);
    const int tid = threadIdx.x;
    const int wid = tid >> 5, lane = tid & 31;
    const int wm = wid >> 2, wn = wid & 3;
    const int grp = lane >> 2, tig = lane & 3;
    const int q0 = blockIdx.x * 2;

    auto loadB = [&](int flat) {
        int st = flat & 1, p = flat >> 2, kt = flat & 3;
#pragma unroll
        for (int j = 0; j < 4; j++) {
            int idx = j * 256 + tid;
            int r = idx >> 3, cc = idx & 7;
            cp16(bs_b + (uint32_t)(st * RELB_STG + r * RELB_STRD + cc * 16),
                 Bi8 + (size_t)(p * 128 + r) * HID + kt * 128 + cc * 16);
        }
        cp_commit();
    };

    loadB(0);

    for (int i = tid; i < HID; i += 256) { sR2b[i] = R2b[i]; sR3w[i] = R3w[i]; }

    // ---- build A: As[row][k] = sat_s8(relu(qp[q][k]+pp[w][k]) * SA_I), swizzled ----
    {
        const int c = tid & 31;
        const int wg = tid >> 5;
        float qv[2][16];
#pragma unroll
        for (int qi = 0; qi < 2; qi++) {
            const bf16* p = qpb + (size_t)(q0 + qi) * HID + c * 16;
            unpk8(*(const uint4*)p, qv[qi]);
            unpk8(*(const uint4*)(p + 8), qv[qi] + 8);
        }
        for (int w = wg * 8; w < wg * 8 + 8; w++) {
            float pv[16];
            const bf16* p = ppb + (size_t)w * HID + c * 16;
            unpk8(*(const uint4*)p, pv);
            unpk8(*(const uint4*)(p + 8), pv + 8);
#pragma unroll
            for (int qi = 0; qi < 2; qi++) {
                int row = qi * 64 + w;
                uint32_t pk[4];
#pragma unroll
                for (int g = 0; g < 4; g++) {
                    int ii[4];
#pragma unroll
                    for (int e = 0; e < 4; e++) {
                        float f = fmaxf(qv[qi][g * 4 + e] + pv[g * 4 + e], 0.f) * SA_I;
                        ii[e] = __float2int_rn(f);
                    }
                    pk[g] = pack_s8x4(ii[0], ii[1], ii[2], ii[3]);
                }
                uint32_t off = (uint32_t)(row * 512 + ((c >> 3) << 7) + (((c ^ row) & 7) << 4));
                *(uint4*)(As8 + off) = make_uint4(pk[0], pk[1], pk[2], pk[3]);
            }
        }
    }

    float rp[8];
#pragma unroll
    for (int j = 0; j < 8; j++) rp[j] = 0.f;

    for (int pass = 0; pass < 4; pass++) {
        const int n0 = pass * 128;
        int ci[4][4][4];
#pragma unroll
        for (int a = 0; a < 4; a++)
#pragma unroll
            for (int b = 0; b < 4; b++)
#pragma unroll
                for (int e = 0; e < 4; e++) ci[a][b][e] = 0;

        for (int kt = 0; kt < 4; kt++) {
            const int flat = pass * 4 + kt;
            if (flat + 1 < 16) { loadB(flat + 1); cp_wait1(); }
            else               { cp_wait0(); }
            __syncthreads();
            const int st = flat & 1;
#pragma unroll
            for (int k32 = 0; k32 < 4; k32++) {
                const int cbase = kt * 8 + k32 * 2;
                uint32_t afr[4][4];
                {
                    const int arow0 = wm * 64 + (lane & 15);
                    const int achk  = cbase + (lane >> 4);
#pragma unroll
                    for (int ms = 0; ms < 4; ms++) {
                        const int arow = arow0 + ms * 16;
                        uint32_t aaddr = as_b + (uint32_t)(arow * 512 + ((achk >> 3) << 7)
                                       + (((achk ^ arow) & 7) << 4));
                        ldmx4(afr[ms][0], afr[ms][1], afr[ms][2], afr[ms][3], aaddr);
                    }
                }
                uint32_t bfr[4][2];
#pragma unroll
                for (int ns = 0; ns < 4; ns++) {
                    const char* p = Bs8 + st * RELB_STG
                                  + (wn * 32 + ns * 8 + grp) * RELB_STRD
                                  + k32 * 32 + tig * 4;
                    bfr[ns][0] = *(const uint32_t*)p;
                    bfr[ns][1] = *(const uint32_t*)(p + 16);
                }
#pragma unroll
                for (int ms = 0; ms < 4; ms++)
#pragma unroll
                    for (int ns = 0; ns < 4; ns++)
                        mma16832_s8(ci[ms][ns], afr[ms][0], afr[ms][1], afr[ms][2], afr[ms][3],
                                    bfr[ns][0], bfr[ns][1]);
            }
            __syncthreads();
        }

#pragma unroll
        for (int ns = 0; ns < 4; ns++) {
            int colbase = n0 + wn * 32 + ns * 8 + tig * 2;
            float bb0 = sR2b[colbase], bb1 = sR2b[colbase + 1];
            float w0 = sR3w[colbase],  w1 = sR3w[colbase + 1];
#pragma unroll
            for (int ms = 0; ms < 4; ms++) {
                rp[ms * 2 + 0] += fmaxf((float)ci[ms][ns][0] * INV_SASB + bb0, 0.f) * w0
                                + fmaxf((float)ci[ms][ns][1] * INV_SASB + bb1, 0.f) * w1;
                rp[ms * 2 + 1] += fmaxf((float)ci[ms][ns][2] * INV_SASB + bb0, 0.f) * w0
                                + fmaxf((float)ci[ms][ns][3] * INV_SASB + bb1, 0.f) * w1;
            }
        }
    }

#pragma unroll
    for (int j = 0; j < 8; j++) {
        rp[j] += __shfl_xor_sync(0xffffffffu, rp[j], 1);
        rp[j] += __shfl_xor_sync(0xffffffffu, rp[j], 2);
    }
    if (tig == 0) {
#pragma unroll
        for (int j = 0; j < 8; j++) {
            int row = wm * 64 + (j >> 1) * 16 + grp + (j & 1) * 8;
            red[row * 4 + wn] = rp[j];
        }
    }
    __syncthreads();
    if (tid < 128) {
        float s = red[tid * 4 + 0] + red[tid * 4 + 1] + red[tid * 4 + 2] + red[tid * 4 + 3]
                + R3b[0];
        out[(size_t)blockIdx.x * 128 + tid] = 1.f / (1.f + expf(-s));
    }
}

// ---------------- host launcher ----------------
extern "C" void kernel_launch(void* const* d_in, const int* in_sizes, int n_in,
                              void* d_out, int out_size)
{
    (void)in_sizes; (void)n_in; (void)out_size;
    const float* support_x = (const float*)d_in[0];
    const int*   support_y = (const int*)d_in[1];
    const float* query_x   = (const float*)d_in[2];
    const float* W1  = (const float*)d_in[3];
    const float* b1  = (const float*)d_in[4];
    const float* W2  = (const float*)d_in[5];
    const float* b2  = (const float*)d_in[6];
    const float* R1w = (const float*)d_in[7];
    const float* R1b = (const float*)d_in[8];
    const float* R2w = (const float*)d_in[9];
    const float* R2b = (const float*)d_in[10];
    const float* R3w = (const float*)d_in[11];
    const float* R3b = (const float*)d_in[12];
    float* out = (float*)d_out;

    bf16 *R1bT, *f, *protosb, *qpb, *ppb;
    signed char *R2i8, *sx8, *qx8, *W1t8, *W2t8, *R1t8, *f1_8, *f8;
    cudaGetSymbolAddress((void**)&sx8, g_sx8);
    cudaGetSymbolAddress((void**)&qx8, g_qx8);
    cudaGetSymbolAddress((void**)&W1t8, g_W1t8);
    cudaGetSymbolAddress((void**)&W2t8, g_W2t8);
    cudaGetSymbolAddress((void**)&R1t8, g_R1t8);
    cudaGetSymbolAddress((void**)&R1bT, g_R1bT);
    cudaGetSymbolAddress((void**)&f1_8, g_f1_8);
    cudaGetSymbolAddress((void**)&f,  g_f);
    cudaGetSymbolAddress((void**)&f8, g_f8);
    cudaGetSymbolAddress((void**)&protosb, g_protosb);
    cudaGetSymbolAddress((void**)&qpb, g_qpb);
    cudaGetSymbolAddress((void**)&ppb, g_ppb);
    cudaGetSymbolAddress((void**)&R2i8, g_R2i8);

    const int GEMM_SMEM = 3 * (9216 + 4608) * 2;  // 82944 B
    cudaFuncSetAttribute(gemm_k<true, false>, cudaFuncAttributeMaxDynamicSharedMemorySize, GEMM_SMEM);
    cudaFuncSetAttribute(gemm_i8<8, true,  true,  true,  false, true >, cudaFuncAttributeMaxDynamicSharedMemorySize, GI_TOTAL);
    cudaFuncSetAttribute(gemm_i8<4, false, true,  true,  true,  true >, cudaFuncAttributeMaxDynamicSharedMemorySize, GI_TOTAL);
    cudaFuncSetAttribute(gemm_i8<4, false, false, false, true,  false>, cudaFuncAttributeMaxDynamicSharedMemorySize, GI_TOTAL);
    cudaFuncSetAttribute(relation_i8, cudaFuncAttributeMaxDynamicSharedMemorySize, REL_TOTAL);

    // 1) quantize both inputs (one launch)
    quant2_s8<<<(M_ALL * D_IN / 4 + 255) / 256, 256>>>(support_x, query_x, sx8, qx8);

    // 2) all weight transposes (one launch)
    prep_weights<<<dim3(32, 16, 5), 256>>>(W1, W2, R1w, R2w, W1t8, W2t8, R1t8, R1bT, R2i8);

    // 3) encoder layer 1 (int8, S || Q) -> f1 int8 (scale 32)
    gemm_i8<8, true, true, true, false, true><<<dim3(8, M_ALL / 128), 256, GI_TOTAL>>>(
        sx8, qx8, W1t8, b1, DQ1, SF1_I, nullptr, f1_8);

    // 4) encoder layer 2 (int8) -> f bf16 + f8 int8 (scale 64)
    gemm_i8<4, false, true, true, true, true><<<dim3(8, M_ALL / 128), 256, GI_TOTAL>>>(
        f1_8, nullptr, W2t8, b2, DQ2, SF_I, f, f8);

    // 5) prototypes (from bf16 support features)
    protos_k<<<WAYS, HID>>>(f, support_y, protosb);

    // 6) relation first-layer halves: pp (bf16, tiny) and qp (int8)
    gemm_k<true, false><<<dim3(8, 1), 256, GEMM_SMEM>>>(protosb, R1bT, R1b, ppb, WAYS, HID);
    gemm_i8<4, false, false, false, true, false><<<dim3(8, Q_N / 128), 256, GI_TOTAL>>>(
        f8 + (size_t)S_N * HID, nullptr, R1t8, nullptr, DQQ, 0.f, qpb, nullptr);

    // 7) fused relation GEMM (int8 IMMA) + R3 reduction + sigmoid
    relation_i8<<<Q_N * WAYS / 128, 256, REL_TOTAL>>>(qpb, ppb, R2i8, R2b, R3w, R3b, out);
}